// round 10
// baseline (speedup 1.0000x reference)
#include <cuda_runtime.h>

#define N_NODE 100000
#define EMB    112
#define NNZ    1000000
#define BATCH  512
#define SEQL   50
#define MAXNEED (BATCH * SEQL)

#define SCAN_BLK 512
#define SCAN_NB  ((N_NODE + SCAN_BLK - 1) / SCAN_BLK)   // 196

// ---------------- scratch (device globals; zero-initialized at load) ---------
__device__ int   g_cnt[N_NODE];               // invariant: 0 on entry (self-reset)
__device__ int   g_row_ptr[N_NODE + 1];       // PARTIAL (block-local) prefix
__device__ int   g_row_fill[N_NODE];          // partial prefix, mutated by scatter
__device__ int   g_blocksum[SCAN_NB];         // scanned block offsets
__device__ int   g_scan_done;                 // invariant: 0 on entry (self-reset)
__device__ int   g_need[MAXNEED];             // row idx or -1; duplicates allowed
__device__ uint2 g_csr[NNZ];                  // interleaved {val, col}
__device__ float g_buf1[(size_t)N_NODE * EMB];
__device__ float g_buf2[(size_t)N_NODE * EMB];
__device__ float g_sess[BATCH * EMB];
__device__ float g_tmp[BATCH * EMB];
__device__ float g_accum[BATCH * EMB];
__device__ float g_DA[BATCH * BATCH];

// ---------------- count (4 edges/thread) + build need list --------------------
__global__ void k_count(const int* __restrict__ rows, const int* __restrict__ items) {
    int i = blockIdx.x * blockDim.x + threadIdx.x;
    if (i < NNZ / 4) {
        int4 r = reinterpret_cast<const int4*>(rows)[i];
        atomicAdd(&g_cnt[r.x], 1);
        atomicAdd(&g_cnt[r.y], 1);
        atomicAdd(&g_cnt[r.z], 1);
        atomicAdd(&g_cnt[r.w], 1);
    }
    if (i < MAXNEED) g_need[i] = items[i] - 1;   // -1 when pad (item==0)
}

// ---------------- scan1 + scan2 fused (last block scans block sums) -----------
// leaves g_row_ptr/g_row_fill as PARTIAL prefixes; g_blocksum holds offsets
__global__ void k_scan12() {
    __shared__ int ws[SCAN_BLK / 32];
    __shared__ int s_last;
    const int tid  = threadIdx.x;
    const int lane = tid & 31;
    const int wid  = tid >> 5;
    const int i    = blockIdx.x * SCAN_BLK + tid;

    int v = (i < N_NODE) ? g_cnt[i] : 0;
    if (i < N_NODE) g_cnt[i] = 0;              // self-reset for next call

    int inc = v;
    #pragma unroll
    for (int off = 1; off < 32; off <<= 1) {
        int t = __shfl_up_sync(0xffffffffu, inc, off);
        if (lane >= off) inc += t;
    }
    if (lane == 31) ws[wid] = inc;
    __syncthreads();
    if (wid == 0) {
        int s = (lane < SCAN_BLK / 32) ? ws[lane] : 0;
        #pragma unroll
        for (int off = 1; off < SCAN_BLK / 32; off <<= 1) {
            int t = __shfl_up_sync(0xffffffffu, s, off);
            if (lane >= off) s += t;
        }
        if (lane < SCAN_BLK / 32) ws[lane] = s;
    }
    __syncthreads();

    int excl = inc - v + (wid > 0 ? ws[wid - 1] : 0);
    if (i < N_NODE) {
        g_row_ptr[i]  = excl;                  // partial
        g_row_fill[i] = excl;                  // partial (scatter adds blocksum)
    }
    if (tid == SCAN_BLK - 1) {
        g_blocksum[blockIdx.x] = excl + v;
        __threadfence();
    }
    __syncthreads();

    if (tid == 0) {
        int t = atomicAdd(&g_scan_done, 1);
        s_last = (t == SCAN_NB - 1);
        if (s_last) g_scan_done = 0;           // self-reset
    }
    __syncthreads();
    if (!s_last) return;

    __syncthreads();
    int v2 = (tid < SCAN_NB) ? g_blocksum[tid] : 0;
    int inc2 = v2;
    #pragma unroll
    for (int off = 1; off < 32; off <<= 1) {
        int t = __shfl_up_sync(0xffffffffu, inc2, off);
        if (lane >= off) inc2 += t;
    }
    if (lane == 31) ws[wid] = inc2;
    __syncthreads();
    if (wid == 0) {
        int s = (lane < SCAN_BLK / 32) ? ws[lane] : 0;
        #pragma unroll
        for (int off = 1; off < SCAN_BLK / 32; off <<= 1) {
            int t = __shfl_up_sync(0xffffffffu, s, off);
            if (lane >= off) s += t;
        }
        if (lane < SCAN_BLK / 32) ws[lane] = s;
    }
    __syncthreads();
    int excl2 = inc2 - v2 + (wid > 0 ? ws[wid - 1] : 0);
    if (tid < SCAN_NB) g_blocksum[tid] = excl2;    // exclusive block offsets
}

// ---------------- scatter (4 edges/thread); applies blocksum lazily ------------
__global__ void k_scatter(const float* __restrict__ vals,
                          const int* __restrict__ rows,
                          const int* __restrict__ cols) {
    int i = blockIdx.x * blockDim.x + threadIdx.x;
    if (i < NNZ / 4) {
        int4   r = reinterpret_cast<const int4*>(rows)[i];
        int4   c = reinterpret_cast<const int4*>(cols)[i];
        float4 v = reinterpret_cast<const float4*>(vals)[i];
        int p;
        p = atomicAdd(&g_row_fill[r.x], 1) + g_blocksum[r.x >> 9];
        g_csr[p] = make_uint2(__float_as_uint(v.x), (unsigned)c.x);
        p = atomicAdd(&g_row_fill[r.y], 1) + g_blocksum[r.y >> 9];
        g_csr[p] = make_uint2(__float_as_uint(v.y), (unsigned)c.y);
        p = atomicAdd(&g_row_fill[r.z], 1) + g_blocksum[r.z >> 9];
        g_csr[p] = make_uint2(__float_as_uint(v.z), (unsigned)c.z);
        p = atomicAdd(&g_row_fill[r.w], 1) + g_blocksum[r.w >> 9];
        g_csr[p] = make_uint2(__float_as_uint(v.w), (unsigned)c.w);
    }
}

// ---------------- SpMM core: ONE warp per block per row ------------------------
__device__ __forceinline__ void spmm_row(int row, const float* __restrict__ x,
                                         float* __restrict__ y, int lane) {
    int s = g_row_ptr[row] + g_blocksum[row >> 9];
    int e = (row + 1 < N_NODE)
              ? g_row_ptr[row + 1] + g_blocksum[(row + 1) >> 9]
              : NNZ;
    bool act = lane < (EMB / 4);
    float4 acc = make_float4(0.f, 0.f, 0.f, 0.f);

    int k = s;
    for (; k + 3 < e; k += 4) {
        uint2 m0 = g_csr[k];
        uint2 m1 = g_csr[k + 1];
        uint2 m2 = g_csr[k + 2];
        uint2 m3 = g_csr[k + 3];
        if (act) {
            float4 a = *reinterpret_cast<const float4*>(x + (size_t)m0.y * EMB + lane * 4);
            float4 b = *reinterpret_cast<const float4*>(x + (size_t)m1.y * EMB + lane * 4);
            float4 c = *reinterpret_cast<const float4*>(x + (size_t)m2.y * EMB + lane * 4);
            float4 d = *reinterpret_cast<const float4*>(x + (size_t)m3.y * EMB + lane * 4);
            float v0 = __uint_as_float(m0.x), v1 = __uint_as_float(m1.x);
            float v2 = __uint_as_float(m2.x), v3 = __uint_as_float(m3.x);
            acc.x += v0 * a.x + v1 * b.x + v2 * c.x + v3 * d.x;
            acc.y += v0 * a.y + v1 * b.y + v2 * c.y + v3 * d.y;
            acc.z += v0 * a.z + v1 * b.z + v2 * c.z + v3 * d.z;
            acc.w += v0 * a.w + v1 * b.w + v2 * c.w + v3 * d.w;
        }
    }
    for (; k < e; k++) {
        uint2 m = g_csr[k];
        if (act) {
            float4 a = *reinterpret_cast<const float4*>(x + (size_t)m.y * EMB + lane * 4);
            float v = __uint_as_float(m.x);
            acc.x += v * a.x; acc.y += v * a.y; acc.z += v * a.z; acc.w += v * a.w;
        }
    }
    if (act)
        *reinterpret_cast<float4*>(y + (size_t)row * EMB + lane * 4) = acc;
}

// 1 warp per block: rows retire independently (no straggler coupling)
__global__ void __launch_bounds__(32) k_spmm1(const float* __restrict__ emb) {
    spmm_row(blockIdx.x, emb, g_buf1, threadIdx.x);
}

__global__ void __launch_bounds__(32) k_spmm2() {
    int row = g_need[blockIdx.x];
    if (row < 0) return;
    spmm_row(row, g_buf1, g_buf2, threadIdx.x);   // dups write identical data
}

// ---------------- session pooling -----------------------------------------------
__global__ void k_pool(const float* __restrict__ emb,
                       const int* __restrict__ items,
                       const float* __restrict__ slen) {
    int b = blockIdx.x;
    int c = threadIdx.x;                       // 112 threads
    float acc = 0.f;
    #pragma unroll 5
    for (int l = 0; l < SEQL; l++) {
        int it = items[b * SEQL + l];
        if (it > 0) {
            size_t o = (size_t)(it - 1) * EMB + c;
            acc += emb[o] + g_buf1[o] + g_buf2[o];
        }
    }
    float v = acc * (1.0f / 3.0f) / slen[b];
    g_sess[b * EMB + c]  = v;
    g_accum[b * EMB + c] = v;
}

// ---------------- DA = D @ A -----------------------------------------------------
__global__ void k_mm512(const float* __restrict__ D, const float* __restrict__ A) {
    __shared__ float sD[32][33];
    __shared__ float sA[32][33];
    int tx = threadIdx.x, ty = threadIdx.y;
    int row = blockIdx.y * 32 + ty;
    int col = blockIdx.x * 32 + tx;
    float acc = 0.f;
    for (int k0 = 0; k0 < 512; k0 += 32) {
        sD[ty][tx] = D[row * 512 + k0 + tx];
        sA[ty][tx] = A[(k0 + ty) * 512 + col];
        __syncthreads();
        #pragma unroll
        for (int k = 0; k < 32; k++) acc += sD[ty][k] * sA[k][tx];
        __syncthreads();
    }
    g_DA[row * 512 + col] = acc;
}

// ---------------- tmp = sess @ W^T -----------------------------------------------
__global__ void k_linear(const float* __restrict__ w) {
    __shared__ float s[EMB];
    int b = blockIdx.x;
    int o = threadIdx.x;                       // 112 threads
    s[o] = g_sess[b * EMB + o];
    __syncthreads();
    float acc = 0.f;
    #pragma unroll 8
    for (int k = 0; k < EMB; k++) acc += s[k] * w[o * EMB + k];
    g_tmp[b * EMB + o] = acc;
}

// ---------------- sess = l2norm(DA @ tmp); per-row, 512 blocks -------------------
__global__ void k_danorm(int last, float* __restrict__ out) {
    int b = blockIdx.x;
    int c = threadIdx.x;                       // 128 threads, 112 active
    float acc = 0.f;
    if (c < EMB) {
        const float* __restrict__ da = &g_DA[b * 512];
        #pragma unroll 8
        for (int j = 0; j < 512; j++) acc += da[j] * g_tmp[j * EMB + c];
    }
    __shared__ float red[128];
    red[threadIdx.x] = (c < EMB) ? acc * acc : 0.f;
    __syncthreads();
    for (int off = 64; off > 0; off >>= 1) {
        if (threadIdx.x < off) red[threadIdx.x] += red[threadIdx.x + off];
        __syncthreads();
    }
    float inv = 1.0f / fmaxf(sqrtf(red[0]), 1e-12f);
    if (c < EMB) {
        float v = acc * inv;
        if (last) {
            out[b * EMB + c] = (g_accum[b * EMB + c] + v) * (1.0f / 3.0f);
        } else {
            g_sess[b * EMB + c]   = v;
            g_accum[b * EMB + c] += v;
        }
    }
}

// ---------------- launch ----------------------------------------------------------
extern "C" void kernel_launch(void* const* d_in, const int* in_sizes, int n_in,
                              void* d_out, int out_size) {
    const float* emb   = (const float*)d_in[0];
    const float* vals  = (const float*)d_in[1];
    const int*   rows  = (const int*)d_in[2];
    const int*   cols  = (const int*)d_in[3];
    const float* D     = (const float*)d_in[4];
    const float* A     = (const float*)d_in[5];
    const int*   items = (const int*)d_in[6];
    const float* slen  = (const float*)d_in[7];
    const float* wsess = (const float*)d_in[8];
    float* out = (float*)d_out;

    (void)in_sizes; (void)n_in; (void)out_size;

    // CSR build (3 launches)
    k_count  <<<(NNZ / 4 + 255) / 256, 256>>>(rows, items);
    k_scan12 <<<SCAN_NB, SCAN_BLK>>>();
    k_scatter<<<(NNZ / 4 + 255) / 256, 256>>>(vals, rows, cols);

    // hyperconv: 1 warp per block per row
    k_spmm1<<<N_NODE, 32>>>(emb);
    k_spmm2<<<MAXNEED, 32>>>();

    // sessconv
    k_pool <<<BATCH, EMB>>>(emb, items, slen);
    k_mm512<<<dim3(16, 16), dim3(32, 32)>>>(D, A);

    k_linear<<<BATCH, EMB>>>(wsess + 0 * EMB * EMB);
    k_danorm<<<BATCH, 128>>>(0, out);
    k_linear<<<BATCH, EMB>>>(wsess + 1 * EMB * EMB);
    k_danorm<<<BATCH, 128>>>(1, out);
}

// round 11
// speedup vs baseline: 1.0726x; 1.0726x over previous
#include <cuda_runtime.h>

#define N_NODE 100000
#define EMB    112
#define NNZ    1000000
#define BATCH  512
#define SEQL   50
#define MAXNEED (BATCH * SEQL)

#define SCAN_BLK 512
#define SCAN_NB  ((N_NODE + SCAN_BLK - 1) / SCAN_BLK)   // 196

// ---------------- scratch (device globals; zero-initialized at load) ---------
__device__ int   g_cnt[N_NODE];               // invariant: 0 on entry (self-reset)
__device__ int   g_row_ptr[N_NODE + 1];       // PARTIAL (block-local) prefix
__device__ int   g_row_fill[N_NODE];          // partial prefix, mutated by scatter
__device__ int   g_blocksum[SCAN_NB];         // scanned block offsets
__device__ int   g_scan_done;                 // invariant: 0 on entry (self-reset)
__device__ int   g_need[MAXNEED];             // row idx or -1; duplicates allowed
__device__ uint2 g_csr[NNZ];                  // interleaved {val, col}
__device__ float g_buf1[(size_t)N_NODE * EMB];
__device__ float g_buf2[(size_t)N_NODE * EMB];
__device__ float g_sess[BATCH * EMB];
__device__ float g_tmp[BATCH * EMB];
__device__ float g_accum[BATCH * EMB];
__device__ float g_DA[BATCH * BATCH];

// ---------------- count (4 edges/thread) + build need list --------------------
__global__ void k_count(const int* __restrict__ rows, const int* __restrict__ items) {
    int i = blockIdx.x * blockDim.x + threadIdx.x;
    if (i < NNZ / 4) {
        int4 r = reinterpret_cast<const int4*>(rows)[i];
        atomicAdd(&g_cnt[r.x], 1);
        atomicAdd(&g_cnt[r.y], 1);
        atomicAdd(&g_cnt[r.z], 1);
        atomicAdd(&g_cnt[r.w], 1);
    }
    if (i < MAXNEED) g_need[i] = items[i] - 1;   // -1 when pad (item==0)
}

// ---------------- scan1 + scan2 fused (last block scans block sums) -----------
__global__ void k_scan12() {
    __shared__ int ws[SCAN_BLK / 32];
    __shared__ int s_last;
    const int tid  = threadIdx.x;
    const int lane = tid & 31;
    const int wid  = tid >> 5;
    const int i    = blockIdx.x * SCAN_BLK + tid;

    int v = (i < N_NODE) ? g_cnt[i] : 0;
    if (i < N_NODE) g_cnt[i] = 0;              // self-reset for next call

    int inc = v;
    #pragma unroll
    for (int off = 1; off < 32; off <<= 1) {
        int t = __shfl_up_sync(0xffffffffu, inc, off);
        if (lane >= off) inc += t;
    }
    if (lane == 31) ws[wid] = inc;
    __syncthreads();
    if (wid == 0) {
        int s = (lane < SCAN_BLK / 32) ? ws[lane] : 0;
        #pragma unroll
        for (int off = 1; off < SCAN_BLK / 32; off <<= 1) {
            int t = __shfl_up_sync(0xffffffffu, s, off);
            if (lane >= off) s += t;
        }
        if (lane < SCAN_BLK / 32) ws[lane] = s;
    }
    __syncthreads();

    int excl = inc - v + (wid > 0 ? ws[wid - 1] : 0);
    if (i < N_NODE) {
        g_row_ptr[i]  = excl;                  // partial
        g_row_fill[i] = excl;                  // partial (scatter adds blocksum)
    }
    if (tid == SCAN_BLK - 1) {
        g_blocksum[blockIdx.x] = excl + v;
        __threadfence();
    }
    __syncthreads();

    if (tid == 0) {
        int t = atomicAdd(&g_scan_done, 1);
        s_last = (t == SCAN_NB - 1);
        if (s_last) g_scan_done = 0;           // self-reset
    }
    __syncthreads();
    if (!s_last) return;

    __syncthreads();
    int v2 = (tid < SCAN_NB) ? g_blocksum[tid] : 0;
    int inc2 = v2;
    #pragma unroll
    for (int off = 1; off < 32; off <<= 1) {
        int t = __shfl_up_sync(0xffffffffu, inc2, off);
        if (lane >= off) inc2 += t;
    }
    if (lane == 31) ws[wid] = inc2;
    __syncthreads();
    if (wid == 0) {
        int s = (lane < SCAN_BLK / 32) ? ws[lane] : 0;
        #pragma unroll
        for (int off = 1; off < SCAN_BLK / 32; off <<= 1) {
            int t = __shfl_up_sync(0xffffffffu, s, off);
            if (lane >= off) s += t;
        }
        if (lane < SCAN_BLK / 32) ws[lane] = s;
    }
    __syncthreads();
    int excl2 = inc2 - v2 + (wid > 0 ? ws[wid - 1] : 0);
    if (tid < SCAN_NB) g_blocksum[tid] = excl2;    // exclusive block offsets
}

// ---------------- scatter (4 edges/thread); applies blocksum lazily ------------
__global__ void k_scatter(const float* __restrict__ vals,
                          const int* __restrict__ rows,
                          const int* __restrict__ cols) {
    int i = blockIdx.x * blockDim.x + threadIdx.x;
    if (i < NNZ / 4) {
        int4   r = reinterpret_cast<const int4*>(rows)[i];
        int4   c = reinterpret_cast<const int4*>(cols)[i];
        float4 v = reinterpret_cast<const float4*>(vals)[i];
        int p;
        p = atomicAdd(&g_row_fill[r.x], 1) + g_blocksum[r.x >> 9];
        g_csr[p] = make_uint2(__float_as_uint(v.x), (unsigned)c.x);
        p = atomicAdd(&g_row_fill[r.y], 1) + g_blocksum[r.y >> 9];
        g_csr[p] = make_uint2(__float_as_uint(v.y), (unsigned)c.y);
        p = atomicAdd(&g_row_fill[r.z], 1) + g_blocksum[r.z >> 9];
        g_csr[p] = make_uint2(__float_as_uint(v.z), (unsigned)c.z);
        p = atomicAdd(&g_row_fill[r.w], 1) + g_blocksum[r.w >> 9];
        g_csr[p] = make_uint2(__float_as_uint(v.w), (unsigned)c.w);
    }
}

// ---------------- SpMM core: warp per row, depth-4 pipeline --------------------
__device__ __forceinline__ void spmm_row(int row, const float* __restrict__ x,
                                         float* __restrict__ y, int lane) {
    int s = g_row_ptr[row] + g_blocksum[row >> 9];
    int e = (row + 1 < N_NODE)
              ? g_row_ptr[row + 1] + g_blocksum[(row + 1) >> 9]
              : NNZ;
    bool act = lane < (EMB / 4);
    float4 acc = make_float4(0.f, 0.f, 0.f, 0.f);

    int k = s;
    for (; k + 3 < e; k += 4) {
        uint2 m0 = g_csr[k];
        uint2 m1 = g_csr[k + 1];
        uint2 m2 = g_csr[k + 2];
        uint2 m3 = g_csr[k + 3];
        if (act) {
            float4 a = *reinterpret_cast<const float4*>(x + (size_t)m0.y * EMB + lane * 4);
            float4 b = *reinterpret_cast<const float4*>(x + (size_t)m1.y * EMB + lane * 4);
            float4 c = *reinterpret_cast<const float4*>(x + (size_t)m2.y * EMB + lane * 4);
            float4 d = *reinterpret_cast<const float4*>(x + (size_t)m3.y * EMB + lane * 4);
            float v0 = __uint_as_float(m0.x), v1 = __uint_as_float(m1.x);
            float v2 = __uint_as_float(m2.x), v3 = __uint_as_float(m3.x);
            acc.x += v0 * a.x + v1 * b.x + v2 * c.x + v3 * d.x;
            acc.y += v0 * a.y + v1 * b.y + v2 * c.y + v3 * d.y;
            acc.z += v0 * a.z + v1 * b.z + v2 * c.z + v3 * d.z;
            acc.w += v0 * a.w + v1 * b.w + v2 * c.w + v3 * d.w;
        }
    }
    for (; k < e; k++) {
        uint2 m = g_csr[k];
        if (act) {
            float4 a = *reinterpret_cast<const float4*>(x + (size_t)m.y * EMB + lane * 4);
            float v = __uint_as_float(m.x);
            acc.x += v * a.x; acc.y += v * a.y; acc.z += v * a.z; acc.w += v * a.w;
        }
    }
    if (act)
        *reinterpret_cast<float4*>(y + (size_t)row * EMB + lane * 4) = acc;
}

// 64-thread blocks: 2 warps, warp-per-row; 32 CTA/SM cap -> up to 64 warps/SM
__global__ void __launch_bounds__(64) k_spmm1(const float* __restrict__ emb) {
    int row = blockIdx.x * 2 + (threadIdx.x >> 5);
    if (row >= N_NODE) return;
    spmm_row(row, emb, g_buf1, threadIdx.x & 31);
}

__global__ void __launch_bounds__(64) k_spmm2() {
    int idx = blockIdx.x * 2 + (threadIdx.x >> 5);
    if (idx >= MAXNEED) return;
    int row = g_need[idx];
    if (row < 0) return;
    spmm_row(row, g_buf1, g_buf2, threadIdx.x & 31);   // dups write identical data
}

// ---------------- session pooling -----------------------------------------------
__global__ void k_pool(const float* __restrict__ emb,
                       const int* __restrict__ items,
                       const float* __restrict__ slen) {
    int b = blockIdx.x;
    int c = threadIdx.x;                       // 112 threads
    float acc = 0.f;
    #pragma unroll 5
    for (int l = 0; l < SEQL; l++) {
        int it = items[b * SEQL + l];
        if (it > 0) {
            size_t o = (size_t)(it - 1) * EMB + c;
            acc += emb[o] + g_buf1[o] + g_buf2[o];
        }
    }
    float v = acc * (1.0f / 3.0f) / slen[b];
    g_sess[b * EMB + c]  = v;
    g_accum[b * EMB + c] = v;
}

// ---------------- DA = D @ A -----------------------------------------------------
__global__ void k_mm512(const float* __restrict__ D, const float* __restrict__ A) {
    __shared__ float sD[32][33];
    __shared__ float sA[32][33];
    int tx = threadIdx.x, ty = threadIdx.y;
    int row = blockIdx.y * 32 + ty;
    int col = blockIdx.x * 32 + tx;
    float acc = 0.f;
    for (int k0 = 0; k0 < 512; k0 += 32) {
        sD[ty][tx] = D[row * 512 + k0 + tx];
        sA[ty][tx] = A[(k0 + ty) * 512 + col];
        __syncthreads();
        #pragma unroll
        for (int k = 0; k < 32; k++) acc += sD[ty][k] * sA[k][tx];
        __syncthreads();
    }
    g_DA[row * 512 + col] = acc;
}

// ---------------- tmp = sess @ W^T -----------------------------------------------
__global__ void k_linear(const float* __restrict__ w) {
    __shared__ float s[EMB];
    int b = blockIdx.x;
    int o = threadIdx.x;                       // 112 threads
    s[o] = g_sess[b * EMB + o];
    __syncthreads();
    float acc = 0.f;
    #pragma unroll 8
    for (int k = 0; k < EMB; k++) acc += s[k] * w[o * EMB + k];
    g_tmp[b * EMB + o] = acc;
}

// ---------------- sess = l2norm(DA @ tmp); per-row, 512 blocks -------------------
__global__ void k_danorm(int last, float* __restrict__ out) {
    int b = blockIdx.x;
    int c = threadIdx.x;                       // 128 threads, 112 active
    float acc = 0.f;
    if (c < EMB) {
        const float* __restrict__ da = &g_DA[b * 512];
        #pragma unroll 8
        for (int j = 0; j < 512; j++) acc += da[j] * g_tmp[j * EMB + c];
    }
    __shared__ float red[128];
    red[threadIdx.x] = (c < EMB) ? acc * acc : 0.f;
    __syncthreads();
    for (int off = 64; off > 0; off >>= 1) {
        if (threadIdx.x < off) red[threadIdx.x] += red[threadIdx.x + off];
        __syncthreads();
    }
    float inv = 1.0f / fmaxf(sqrtf(red[0]), 1e-12f);
    if (c < EMB) {
        float v = acc * inv;
        if (last) {
            out[b * EMB + c] = (g_accum[b * EMB + c] + v) * (1.0f / 3.0f);
        } else {
            g_sess[b * EMB + c]   = v;
            g_accum[b * EMB + c] += v;
        }
    }
}

// ---------------- launch ----------------------------------------------------------
extern "C" void kernel_launch(void* const* d_in, const int* in_sizes, int n_in,
                              void* d_out, int out_size) {
    const float* emb   = (const float*)d_in[0];
    const float* vals  = (const float*)d_in[1];
    const int*   rows  = (const int*)d_in[2];
    const int*   cols  = (const int*)d_in[3];
    const float* D     = (const float*)d_in[4];
    const float* A     = (const float*)d_in[5];
    const int*   items = (const int*)d_in[6];
    const float* slen  = (const float*)d_in[7];
    const float* wsess = (const float*)d_in[8];
    float* out = (float*)d_out;

    (void)in_sizes; (void)n_in; (void)out_size;

    // CSR build (3 launches)
    k_count  <<<(NNZ / 4 + 255) / 256, 256>>>(rows, items);
    k_scan12 <<<SCAN_NB, SCAN_BLK>>>();
    k_scatter<<<(NNZ / 4 + 255) / 256, 256>>>(vals, rows, cols);

    // hyperconv: 2 warps per block, warp per row
    k_spmm1<<<(N_NODE + 1) / 2, 64>>>(emb);
    k_spmm2<<<(MAXNEED + 1) / 2, 64>>>();

    // sessconv
    k_pool <<<BATCH, EMB>>>(emb, items, slen);
    k_mm512<<<dim3(16, 16), dim3(32, 32)>>>(D, A);

    k_linear<<<BATCH, EMB>>>(wsess + 0 * EMB * EMB);
    k_danorm<<<BATCH, 128>>>(0, out);
    k_linear<<<BATCH, EMB>>>(wsess + 1 * EMB * EMB);
    k_danorm<<<BATCH, 128>>>(1, out);
}

// round 12
// speedup vs baseline: 1.0818x; 1.0086x over previous
#include <cuda_runtime.h>

#define N_NODE 100000
#define EMB    112
#define BSTRIDE 128                            // padded row stride for buf1/buf2
#define NNZ    1000000
#define BATCH  512
#define SEQL   50
#define MAXNEED (BATCH * SEQL)

#define SCAN_BLK 512
#define SCAN_NB  ((N_NODE + SCAN_BLK - 1) / SCAN_BLK)   // 196

// ---------------- scratch (device globals; zero-initialized at load) ---------
__device__ int   g_cnt[N_NODE];               // invariant: 0 on entry (self-reset)
__device__ int   g_row_ptr[N_NODE + 1];       // PARTIAL (block-local) prefix
__device__ int   g_row_fill[N_NODE];          // partial prefix, mutated by scatter
__device__ int   g_blocksum[SCAN_NB];         // scanned block offsets
__device__ int   g_scan_done;                 // invariant: 0 on entry (self-reset)
__device__ int   g_need[MAXNEED];             // row idx or -1; duplicates allowed
__device__ uint2 g_csr[NNZ];                  // interleaved {val, col}
__device__ float g_buf1[(size_t)N_NODE * BSTRIDE];
__device__ float g_buf2[(size_t)N_NODE * BSTRIDE];
__device__ float g_sess[BATCH * EMB];
__device__ float g_tmp[BATCH * EMB];
__device__ float g_accum[BATCH * EMB];
__device__ float g_DA[BATCH * BATCH];

// ---------------- count (4 edges/thread) + build need list --------------------
__global__ void k_count(const int* __restrict__ rows, const int* __restrict__ items) {
    int i = blockIdx.x * blockDim.x + threadIdx.x;
    if (i < NNZ / 4) {
        int4 r = reinterpret_cast<const int4*>(rows)[i];
        atomicAdd(&g_cnt[r.x], 1);
        atomicAdd(&g_cnt[r.y], 1);
        atomicAdd(&g_cnt[r.z], 1);
        atomicAdd(&g_cnt[r.w], 1);
    }
    if (i < MAXNEED) g_need[i] = items[i] - 1;   // -1 when pad (item==0)
}

// ---------------- scan1 + scan2 fused (last block scans block sums) -----------
__global__ void k_scan12() {
    __shared__ int ws[SCAN_BLK / 32];
    __shared__ int s_last;
    const int tid  = threadIdx.x;
    const int lane = tid & 31;
    const int wid  = tid >> 5;
    const int i    = blockIdx.x * SCAN_BLK + tid;

    int v = (i < N_NODE) ? g_cnt[i] : 0;
    if (i < N_NODE) g_cnt[i] = 0;              // self-reset for next call

    int inc = v;
    #pragma unroll
    for (int off = 1; off < 32; off <<= 1) {
        int t = __shfl_up_sync(0xffffffffu, inc, off);
        if (lane >= off) inc += t;
    }
    if (lane == 31) ws[wid] = inc;
    __syncthreads();
    if (wid == 0) {
        int s = (lane < SCAN_BLK / 32) ? ws[lane] : 0;
        #pragma unroll
        for (int off = 1; off < SCAN_BLK / 32; off <<= 1) {
            int t = __shfl_up_sync(0xffffffffu, s, off);
            if (lane >= off) s += t;
        }
        if (lane < SCAN_BLK / 32) ws[lane] = s;
    }
    __syncthreads();

    int excl = inc - v + (wid > 0 ? ws[wid - 1] : 0);
    if (i < N_NODE) {
        g_row_ptr[i]  = excl;                  // partial
        g_row_fill[i] = excl;                  // partial (scatter adds blocksum)
    }
    if (tid == SCAN_BLK - 1) {
        g_blocksum[blockIdx.x] = excl + v;
        __threadfence();
    }
    __syncthreads();

    if (tid == 0) {
        int t = atomicAdd(&g_scan_done, 1);
        s_last = (t == SCAN_NB - 1);
        if (s_last) g_scan_done = 0;           // self-reset
    }
    __syncthreads();
    if (!s_last) return;

    __syncthreads();
    int v2 = (tid < SCAN_NB) ? g_blocksum[tid] : 0;
    int inc2 = v2;
    #pragma unroll
    for (int off = 1; off < 32; off <<= 1) {
        int t = __shfl_up_sync(0xffffffffu, inc2, off);
        if (lane >= off) inc2 += t;
    }
    if (lane == 31) ws[wid] = inc2;
    __syncthreads();
    if (wid == 0) {
        int s = (lane < SCAN_BLK / 32) ? ws[lane] : 0;
        #pragma unroll
        for (int off = 1; off < SCAN_BLK / 32; off <<= 1) {
            int t = __shfl_up_sync(0xffffffffu, s, off);
            if (lane >= off) s += t;
        }
        if (lane < SCAN_BLK / 32) ws[lane] = s;
    }
    __syncthreads();
    int excl2 = inc2 - v2 + (wid > 0 ? ws[wid - 1] : 0);
    if (tid < SCAN_NB) g_blocksum[tid] = excl2;    // exclusive block offsets
}

// ---------------- scatter (4 edges/thread); applies blocksum lazily ------------
__global__ void k_scatter(const float* __restrict__ vals,
                          const int* __restrict__ rows,
                          const int* __restrict__ cols) {
    int i = blockIdx.x * blockDim.x + threadIdx.x;
    if (i < NNZ / 4) {
        int4   r = reinterpret_cast<const int4*>(rows)[i];
        int4   c = reinterpret_cast<const int4*>(cols)[i];
        float4 v = reinterpret_cast<const float4*>(vals)[i];
        int p;
        p = atomicAdd(&g_row_fill[r.x], 1) + g_blocksum[r.x >> 9];
        g_csr[p] = make_uint2(__float_as_uint(v.x), (unsigned)c.x);
        p = atomicAdd(&g_row_fill[r.y], 1) + g_blocksum[r.y >> 9];
        g_csr[p] = make_uint2(__float_as_uint(v.y), (unsigned)c.y);
        p = atomicAdd(&g_row_fill[r.z], 1) + g_blocksum[r.z >> 9];
        g_csr[p] = make_uint2(__float_as_uint(v.z), (unsigned)c.z);
        p = atomicAdd(&g_row_fill[r.w], 1) + g_blocksum[r.w >> 9];
        g_csr[p] = make_uint2(__float_as_uint(v.w), (unsigned)c.w);
    }
}

// ---------------- SpMM core: warp per row, depth-2 (low-reg) -------------------
__device__ __forceinline__ void spmm_row(int row, const float* __restrict__ x,
                                         int xs, float* __restrict__ y, int lane) {
    int s = g_row_ptr[row] + g_blocksum[row >> 9];
    int e = (row + 1 < N_NODE)
              ? g_row_ptr[row + 1] + g_blocksum[(row + 1) >> 9]
              : NNZ;
    bool act = lane < (EMB / 4);
    float4 acc = make_float4(0.f, 0.f, 0.f, 0.f);

    int k = s;
    for (; k + 1 < e; k += 2) {
        uint2 m0 = g_csr[k];
        uint2 m1 = g_csr[k + 1];
        if (act) {
            float4 a = *reinterpret_cast<const float4*>(x + (size_t)m0.y * xs + lane * 4);
            float4 b = *reinterpret_cast<const float4*>(x + (size_t)m1.y * xs + lane * 4);
            float v0 = __uint_as_float(m0.x), v1 = __uint_as_float(m1.x);
            acc.x += v0 * a.x + v1 * b.x;
            acc.y += v0 * a.y + v1 * b.y;
            acc.z += v0 * a.z + v1 * b.z;
            acc.w += v0 * a.w + v1 * b.w;
        }
    }
    if (k < e) {
        uint2 m = g_csr[k];
        if (act) {
            float4 a = *reinterpret_cast<const float4*>(x + (size_t)m.y * xs + lane * 4);
            float v = __uint_as_float(m.x);
            acc.x += v * a.x; acc.y += v * a.y; acc.z += v * a.z; acc.w += v * a.w;
        }
    }
    if (act)
        *reinterpret_cast<float4*>(y + (size_t)row * BSTRIDE + lane * 4) = acc;
}

// 64-thread blocks, warp-per-row, forced 32 CTA/SM => 64 warps/SM ceiling
__global__ void __launch_bounds__(64, 32) k_spmm1(const float* __restrict__ emb) {
    int row = blockIdx.x * 2 + (threadIdx.x >> 5);
    if (row >= N_NODE) return;
    spmm_row(row, emb, EMB, g_buf1, threadIdx.x & 31);
}

__global__ void __launch_bounds__(64, 32) k_spmm2() {
    int idx = blockIdx.x * 2 + (threadIdx.x >> 5);
    if (idx >= MAXNEED) return;
    int row = g_need[idx];
    if (row < 0) return;
    spmm_row(row, g_buf1, BSTRIDE, g_buf2, threadIdx.x & 31);   // dups benign
}

// ---------------- session pooling -----------------------------------------------
__global__ void k_pool(const float* __restrict__ emb,
                       const int* __restrict__ items,
                       const float* __restrict__ slen) {
    int b = blockIdx.x;
    int c = threadIdx.x;                       // 112 threads
    float acc = 0.f;
    #pragma unroll 5
    for (int l = 0; l < SEQL; l++) {
        int it = items[b * SEQL + l];
        if (it > 0) {
            int row = it - 1;
            acc += emb[(size_t)row * EMB + c]
                 + g_buf1[(size_t)row * BSTRIDE + c]
                 + g_buf2[(size_t)row * BSTRIDE + c];
        }
    }
    float v = acc * (1.0f / 3.0f) / slen[b];
    g_sess[b * EMB + c]  = v;
    g_accum[b * EMB + c] = v;
}

// ---------------- DA = D @ A -----------------------------------------------------
__global__ void k_mm512(const float* __restrict__ D, const float* __restrict__ A) {
    __shared__ float sD[32][33];
    __shared__ float sA[32][33];
    int tx = threadIdx.x, ty = threadIdx.y;
    int row = blockIdx.y * 32 + ty;
    int col = blockIdx.x * 32 + tx;
    float acc = 0.f;
    for (int k0 = 0; k0 < 512; k0 += 32) {
        sD[ty][tx] = D[row * 512 + k0 + tx];
        sA[ty][tx] = A[(k0 + ty) * 512 + col];
        __syncthreads();
        #pragma unroll
        for (int k = 0; k < 32; k++) acc += sD[ty][k] * sA[k][tx];
        __syncthreads();
    }
    g_DA[row * 512 + col] = acc;
}

// ---------------- tmp = sess @ W^T -----------------------------------------------
__global__ void k_linear(const float* __restrict__ w) {
    __shared__ float s[EMB];
    int b = blockIdx.x;
    int o = threadIdx.x;                       // 112 threads
    s[o] = g_sess[b * EMB + o];
    __syncthreads();
    float acc = 0.f;
    #pragma unroll 8
    for (int k = 0; k < EMB; k++) acc += s[k] * w[o * EMB + k];
    g_tmp[b * EMB + o] = acc;
}

// ---------------- sess = l2norm(DA @ tmp); per-row, 512 blocks -------------------
__global__ void k_danorm(int last, float* __restrict__ out) {
    int b = blockIdx.x;
    int c = threadIdx.x;                       // 128 threads, 112 active
    float acc = 0.f;
    if (c < EMB) {
        const float* __restrict__ da = &g_DA[b * 512];
        #pragma unroll 8
        for (int j = 0; j < 512; j++) acc += da[j] * g_tmp[j * EMB + c];
    }
    __shared__ float red[128];
    red[threadIdx.x] = (c < EMB) ? acc * acc : 0.f;
    __syncthreads();
    for (int off = 64; off > 0; off >>= 1) {
        if (threadIdx.x < off) red[threadIdx.x] += red[threadIdx.x + off];
        __syncthreads();
    }
    float inv = 1.0f / fmaxf(sqrtf(red[0]), 1e-12f);
    if (c < EMB) {
        float v = acc * inv;
        if (last) {
            out[b * EMB + c] = (g_accum[b * EMB + c] + v) * (1.0f / 3.0f);
        } else {
            g_sess[b * EMB + c]   = v;
            g_accum[b * EMB + c] += v;
        }
    }
}

// ---------------- launch ----------------------------------------------------------
extern "C" void kernel_launch(void* const* d_in, const int* in_sizes, int n_in,
                              void* d_out, int out_size) {
    const float* emb   = (const float*)d_in[0];
    const float* vals  = (const float*)d_in[1];
    const int*   rows  = (const int*)d_in[2];
    const int*   cols  = (const int*)d_in[3];
    const float* D     = (const float*)d_in[4];
    const float* A     = (const float*)d_in[5];
    const int*   items = (const int*)d_in[6];
    const float* slen  = (const float*)d_in[7];
    const float* wsess = (const float*)d_in[8];
    float* out = (float*)d_out;

    (void)in_sizes; (void)n_in; (void)out_size;

    // CSR build (3 launches)
    k_count  <<<(NNZ / 4 + 255) / 256, 256>>>(rows, items);
    k_scan12 <<<SCAN_NB, SCAN_BLK>>>();
    k_scatter<<<(NNZ / 4 + 255) / 256, 256>>>(vals, rows, cols);

    // hyperconv: 2 warps per block, warp per row
    k_spmm1<<<(N_NODE + 1) / 2, 64>>>(emb);
    k_spmm2<<<(MAXNEED + 1) / 2, 64>>>();

    // sessconv
    k_pool <<<BATCH, EMB>>>(emb, items, slen);
    k_mm512<<<dim3(16, 16), dim3(32, 32)>>>(D, A);

    k_linear<<<BATCH, EMB>>>(wsess + 0 * EMB * EMB);
    k_danorm<<<BATCH, 128>>>(0, out);
    k_linear<<<BATCH, EMB>>>(wsess + 1 * EMB * EMB);
    k_danorm<<<BATCH, 128>>>(1, out);
}